// round 9
// baseline (speedup 1.0000x reference)
#include <cuda_runtime.h>
#include <cuda_bf16.h>

// Patch2Im (col2im / fold), residue-specialized gather, residue-pure warps.
// in : [256 (b*c), 7 (i), 7 (j), 85 (nh), 85 (nw)] f32
// out: [256, 253, 253] f32
//
// Uncropped y = h + 3; contributing slots (i = y-3*nh):
//   A: i=ry,   nh=my    (valid iff my<=84)
//   B: i=ry+3, nh=my-1  (always)
//   C: i=ry+6, nh=my-2  (valid iff ry==0 && my>=2)
// ry=h%3, my=h/3+1; same structure in x with rx=w%3, m=w/3+1.
// Block layout: 288 threads, rx = tid/96 (warps are residue-pure so every
// slot load is 32 consecutive floats), m = tid%96 + 1.
// Output row staged in smem (stride-3 write, conflict-free) then written
// coalesced by threads 0..252.

#define NHW 85
#define PLANE (NHW * NHW)        // 7225
#define CPLANE (49 * PLANE)      // floats per (b,c) plane
#define WOUT 253
#define HOUT 253
#define SPATIAL (WOUT * HOUT)

__global__ __launch_bounds__(288) void patch2im_kernel(
    const float* __restrict__ in, float* __restrict__ out)
{
    const int tid = threadIdx.x;
    const int h  = blockIdx.x;      // 0..252
    const int bc = blockIdx.y;      // 0..127 -> planes bc and bc+128

    // ---- row-uniform (block-uniform -> uniform regs) ----
    const int ry = h % 3;
    const int my = h / 3 + 1;                  // 1..85
    const bool prA = (my <= 84);
    const bool prC = (ry == 0) && (my >= 2);
    const int row0 = (ry * 7) * PLANE + my * NHW;
    const int row1 = ((ry + 3) * 7) * PLANE + (my - 1) * NHW;
    const int row2 = ((ry + 6) * 7) * PLANE + (my - 2) * NHW;

    __shared__ float srow[2][256];

    // ---- residue-pure per-thread mapping ----
    const int rx = tid / 96;        // 0,1,2 (warp-pure: 96 = 3 warps)
    const int t  = tid - rx * 96;   // 0..95
    const int m  = t + 1;           // nw-index for slot A
    const int mmax = (rx == 0) ? 85 : 84;

    if (m <= mmax) {
        const bool pcA = (m <= 84);
        const bool pcC = (rx == 0) && (m >= 2);
        const int colA = rx * PLANE + m;
        const int colB = (rx + 3) * PLANE + (m - 1);
        const int colC = (rx + 6) * PLANE + (m - 2);

        const float* __restrict__ p0 = in + (size_t)bc * CPLANE;
        const float* __restrict__ p1 = p0 + (size_t)128 * CPLANE;

        float a0 = 0.f, a1 = 0.f, a2 = 0.f, a3 = 0.f, a4 = 0.f,
              a5 = 0.f, a6 = 0.f, a7 = 0.f, a8 = 0.f;
        float b0 = 0.f, b1 = 0.f, b2 = 0.f, b3 = 0.f, b4 = 0.f,
              b5 = 0.f, b6 = 0.f, b7 = 0.f, b8 = 0.f;

        if (prA && pcA) { int o = row0 + colA; a0 = __ldg(p0 + o); b0 = __ldg(p1 + o); }
        if (prA)        { int o = row0 + colB; a1 = __ldg(p0 + o); b1 = __ldg(p1 + o); }
        if (prA && pcC) { int o = row0 + colC; a2 = __ldg(p0 + o); b2 = __ldg(p1 + o); }
        if (pcA)        { int o = row1 + colA; a3 = __ldg(p0 + o); b3 = __ldg(p1 + o); }
        {               int o = row1 + colB; a4 = __ldg(p0 + o); b4 = __ldg(p1 + o); }
        if (pcC)        { int o = row1 + colC; a5 = __ldg(p0 + o); b5 = __ldg(p1 + o); }
        if (prC && pcA) { int o = row2 + colA; a6 = __ldg(p0 + o); b6 = __ldg(p1 + o); }
        if (prC)        { int o = row2 + colB; a7 = __ldg(p0 + o); b7 = __ldg(p1 + o); }
        if (prC && pcC) { int o = row2 + colC; a8 = __ldg(p0 + o); b8 = __ldg(p1 + o); }

        const int cnt = (1 + (int)prA + (int)prC) * (1 + (int)pcA + (int)pcC);
        const float inv = 1.0f / (float)cnt;

        const float s0 = ((a0 + a1) + (a2 + a3)) + ((a4 + a5) + (a6 + a7)) + a8;
        const float s1 = ((b0 + b1) + (b2 + b3)) + ((b4 + b5) + (b6 + b7)) + b8;

        const int w = 3 * t + rx;   // output column, stride-3 smem write (conflict-free)
        srow[0][w] = s0 * inv;
        srow[1][w] = s1 * inv;
    }
    __syncthreads();

    if (tid < WOUT) {
        const size_t obase = (size_t)bc * SPATIAL + (size_t)h * WOUT + tid;
        out[obase] = srow[0][tid];
        out[obase + (size_t)128 * SPATIAL] = srow[1][tid];
    }
}

extern "C" void kernel_launch(void* const* d_in, const int* in_sizes, int n_in,
                              void* d_out, int out_size)
{
    const float* in = (const float*)d_in[0];
    float* out = (float*)d_out;
    dim3 grid(HOUT, 128);   // (253 rows, 128 bc-pairs)
    patch2im_kernel<<<grid, 288>>>(in, out);
}

// round 10
// speedup vs baseline: 1.0306x; 1.0306x over previous
#include <cuda_runtime.h>
#include <cuda_bf16.h>

// Patch2Im (col2im / fold), residue-specialized gather.
// in : [256 (b*c), 7 (i), 7 (j), 85 (nh), 85 (nw)] f32
// out: [256, 253, 253] f32
//
// Uncropped y = h + 3; contributing slots (i = y-3*nh):
//   A: i=ry,   nh=my    (valid iff my<=84)
//   B: i=ry+3, nh=my-1  (always)
//   C: i=ry+6, nh=my-2  (valid iff ry==0 && my>=2)
// ry=h%3, my=h/3+1; same in x with rx=w%3, m=w/3+1.
//
// Each thread: 1 column x 2 rows x 2 bc-planes = 4 outputs, 36 independent
// predicated loads. Column math (div/mod/predicates/offsets) computed ONCE
// and shared across both rows; row math is block-uniform (uniform regs).

#define NHW 85
#define PLANE (NHW * NHW)        // 7225
#define CPLANE (49 * PLANE)      // floats per (b,c) plane
#define WOUT 253
#define HOUT 253
#define SPATIAL (WOUT * HOUT)

__global__ __launch_bounds__(256) void patch2im_kernel(
    const float* __restrict__ in, float* __restrict__ out)
{
    const int w  = threadIdx.x;
    const int h0 = blockIdx.x * 2;      // rows h0, h0+1
    const int bc = blockIdx.y;          // planes bc, bc+128
    if (w >= WOUT) return;

    // ---- per-thread column math (shared across both rows) ----
    const int rx = w % 3;
    const int m  = w / 3 + 1;                  // 1..85
    const bool pcA = (m <= 84);
    const bool pcC = (rx == 0) && (m >= 2);
    const int colA = rx * PLANE + m;
    const int colB = (rx + 3) * PLANE + (m - 1);
    const int colC = (rx + 6) * PLANE + (m - 2);
    const int ccnt = 1 + (int)pcA + (int)pcC;

    // ---- row-uniform math (uniform regs) ----
    const int ry0 = h0 % 3;
    const int my0 = h0 / 3 + 1;
    const bool prA0 = (my0 <= 84);
    const bool prC0 = (ry0 == 0) && (my0 >= 2);
    const int r00 = (ry0 * 7) * PLANE + my0 * NHW;
    const int r01 = ((ry0 + 3) * 7) * PLANE + (my0 - 1) * NHW;
    const int r02 = ((ry0 + 6) * 7) * PLANE + (my0 - 2) * NHW;

    const int h1 = h0 + 1;
    const bool hv1 = (h1 < HOUT);
    const int ry1 = h1 % 3;
    const int my1 = h1 / 3 + 1;
    const bool prA1 = hv1 && (my1 <= 84);
    const bool prB1 = hv1;
    const bool prC1 = hv1 && (ry1 == 0) && (my1 >= 2);
    const int r10 = (ry1 * 7) * PLANE + my1 * NHW;
    const int r11 = ((ry1 + 3) * 7) * PLANE + (my1 - 1) * NHW;
    const int r12 = ((ry1 + 6) * 7) * PLANE + (my1 - 2) * NHW;

    const float* __restrict__ p0 = in + (size_t)bc * CPLANE;
    const float* __restrict__ p1 = p0 + (size_t)128 * CPLANE;

    // ---- 36 independent predicated loads ----
    float a0=0.f,a1=0.f,a2=0.f,a3=0.f,a4=0.f,a5=0.f,a6=0.f,a7=0.f,a8=0.f;  // row0 plane0
    float b0=0.f,b1=0.f,b2=0.f,b3=0.f,b4=0.f,b5=0.f,b6=0.f,b7=0.f,b8=0.f;  // row0 plane1
    float c0=0.f,c1=0.f,c2=0.f,c3=0.f,c4=0.f,c5=0.f,c6=0.f,c7=0.f,c8=0.f;  // row1 plane0
    float d0=0.f,d1=0.f,d2=0.f,d3=0.f,d4=0.f,d5=0.f,d6=0.f,d7=0.f,d8=0.f;  // row1 plane1

    if (prA0 && pcA) { int o = r00 + colA; a0 = __ldg(p0 + o); b0 = __ldg(p1 + o); }
    if (prA0)        { int o = r00 + colB; a1 = __ldg(p0 + o); b1 = __ldg(p1 + o); }
    if (prA0 && pcC) { int o = r00 + colC; a2 = __ldg(p0 + o); b2 = __ldg(p1 + o); }
    if (pcA)         { int o = r01 + colA; a3 = __ldg(p0 + o); b3 = __ldg(p1 + o); }
    {                int o = r01 + colB; a4 = __ldg(p0 + o); b4 = __ldg(p1 + o); }
    if (pcC)         { int o = r01 + colC; a5 = __ldg(p0 + o); b5 = __ldg(p1 + o); }
    if (prC0 && pcA) { int o = r02 + colA; a6 = __ldg(p0 + o); b6 = __ldg(p1 + o); }
    if (prC0)        { int o = r02 + colB; a7 = __ldg(p0 + o); b7 = __ldg(p1 + o); }
    if (prC0 && pcC) { int o = r02 + colC; a8 = __ldg(p0 + o); b8 = __ldg(p1 + o); }

    if (prA1 && pcA) { int o = r10 + colA; c0 = __ldg(p0 + o); d0 = __ldg(p1 + o); }
    if (prA1)        { int o = r10 + colB; c1 = __ldg(p0 + o); d1 = __ldg(p1 + o); }
    if (prA1 && pcC) { int o = r10 + colC; c2 = __ldg(p0 + o); d2 = __ldg(p1 + o); }
    if (prB1 && pcA) { int o = r11 + colA; c3 = __ldg(p0 + o); d3 = __ldg(p1 + o); }
    if (prB1)        { int o = r11 + colB; c4 = __ldg(p0 + o); d4 = __ldg(p1 + o); }
    if (prB1 && pcC) { int o = r11 + colC; c5 = __ldg(p0 + o); d5 = __ldg(p1 + o); }
    if (prC1 && pcA) { int o = r12 + colA; c6 = __ldg(p0 + o); d6 = __ldg(p1 + o); }
    if (prC1)        { int o = r12 + colB; c7 = __ldg(p0 + o); d7 = __ldg(p1 + o); }
    if (prC1 && pcC) { int o = r12 + colC; c8 = __ldg(p0 + o); d8 = __ldg(p1 + o); }

    const float inv0 = 1.0f / (float)((1 + (int)prA0 + (int)prC0) * ccnt);
    const float s0 = ((a0 + a1) + (a2 + a3)) + ((a4 + a5) + (a6 + a7)) + a8;
    const float t0 = ((b0 + b1) + (b2 + b3)) + ((b4 + b5) + (b6 + b7)) + b8;

    const size_t ob0 = (size_t)bc * SPATIAL + (size_t)h0 * WOUT + w;
    out[ob0] = s0 * inv0;
    out[ob0 + (size_t)128 * SPATIAL] = t0 * inv0;

    if (hv1) {
        const float inv1 = 1.0f / (float)((1 + (int)(my1 <= 84) + (int)((ry1 == 0) && (my1 >= 2))) * ccnt);
        const float s1 = ((c0 + c1) + (c2 + c3)) + ((c4 + c5) + (c6 + c7)) + c8;
        const float t1 = ((d0 + d1) + (d2 + d3)) + ((d4 + d5) + (d6 + d7)) + d8;
        const size_t ob1 = ob0 + WOUT;
        out[ob1] = s1 * inv1;
        out[ob1 + (size_t)128 * SPATIAL] = t1 * inv1;
    }
}

extern "C" void kernel_launch(void* const* d_in, const int* in_sizes, int n_in,
                              void* d_out, int out_size)
{
    const float* in = (const float*)d_in[0];
    float* out = (float*)d_out;
    dim3 grid((HOUT + 1) / 2, 128);   // (127 row-pairs, 128 bc-pairs)
    patch2im_kernel<<<grid, 256>>>(in, out);
}

// round 13
// speedup vs baseline: 1.1204x; 1.0871x over previous
#include <cuda_runtime.h>
#include <cuda_bf16.h>

// Patch2Im (col2im / fold), residue-specialized gather, residue-pure warps,
// direct stride-3 stores (no smem, no barrier).
// in : [256 (b*c), 7 (i), 7 (j), 85 (nh), 85 (nw)] f32
// out: [256, 253, 253] f32
//
// Uncropped y = h + 3; contributing slots (i = y-3*nh):
//   A: i=ry,   nh=my    (valid iff my<=84)
//   B: i=ry+3, nh=my-1  (always)
//   C: i=ry+6, nh=my-2  (valid iff ry==0 && my>=2)
// ry=h%3, my=h/3+1; same structure in x with rx=w%3, m=w/3+1.
//
// Block: 288 threads, rx = tid/96 (each warp residue-pure: all 32 lanes share
// rx, consecutive m). Every slot load is 32 consecutive floats -> <=2 L1
// wavefronts per LDG (vs ~6 for residue-mixed warps). Output column
// w = 3*t + rx stored directly (stride-3; L2 write-combines across the three
// residue warps of the block).

#define NHW 85
#define PLANE (NHW * NHW)        // 7225
#define CPLANE (49 * PLANE)      // floats per (b,c) plane
#define WOUT 253
#define HOUT 253
#define SPATIAL (WOUT * HOUT)

__global__ __launch_bounds__(288) void patch2im_kernel(
    const float* __restrict__ in, float* __restrict__ out)
{
    const int tid = threadIdx.x;
    const int h  = blockIdx.x;      // 0..252
    const int bc = blockIdx.y;      // 0..127 -> planes bc and bc+128

    // ---- row-uniform math (block-uniform -> uniform regs) ----
    const int ry = h % 3;
    const int my = h / 3 + 1;                  // 1..85
    const bool prA = (my <= 84);
    const bool prC = (ry == 0) && (my >= 2);
    const int row0 = (ry * 7) * PLANE + my * NHW;
    const int row1 = ((ry + 3) * 7) * PLANE + (my - 1) * NHW;
    const int row2 = ((ry + 6) * 7) * PLANE + (my - 2) * NHW;

    // ---- residue-pure per-thread mapping ----
    const int rx = tid / 96;        // 0,1,2  (96 = 3 full warps per residue)
    const int t  = tid - rx * 96;   // 0..95
    const int m  = t + 1;           // nw-index for slot A
    const int mmax = (rx == 0) ? 85 : 84;
    if (m > mmax) return;           // 11-12 tail lanes idle per residue

    const bool pcA = (m <= 84);
    const bool pcC = (rx == 0) && (m >= 2);
    const int colA = rx * PLANE + m;
    const int colB = (rx + 3) * PLANE + (m - 1);
    const int colC = (rx + 6) * PLANE + (m - 2);

    const float* __restrict__ p0 = in + (size_t)bc * CPLANE;
    const float* __restrict__ p1 = p0 + (size_t)128 * CPLANE;

    // ---- 9 predicated loads x 2 planes (independent -> MLP 18) ----
    float a0 = 0.f, a1 = 0.f, a2 = 0.f, a3 = 0.f, a4 = 0.f,
          a5 = 0.f, a6 = 0.f, a7 = 0.f, a8 = 0.f;
    float b0 = 0.f, b1 = 0.f, b2 = 0.f, b3 = 0.f, b4 = 0.f,
          b5 = 0.f, b6 = 0.f, b7 = 0.f, b8 = 0.f;

    if (prA && pcA) { int o = row0 + colA; a0 = __ldg(p0 + o); b0 = __ldg(p1 + o); }
    if (prA)        { int o = row0 + colB; a1 = __ldg(p0 + o); b1 = __ldg(p1 + o); }
    if (prA && pcC) { int o = row0 + colC; a2 = __ldg(p0 + o); b2 = __ldg(p1 + o); }
    if (pcA)        { int o = row1 + colA; a3 = __ldg(p0 + o); b3 = __ldg(p1 + o); }
    {               int o = row1 + colB; a4 = __ldg(p0 + o); b4 = __ldg(p1 + o); }
    if (pcC)        { int o = row1 + colC; a5 = __ldg(p0 + o); b5 = __ldg(p1 + o); }
    if (prC && pcA) { int o = row2 + colA; a6 = __ldg(p0 + o); b6 = __ldg(p1 + o); }
    if (prC)        { int o = row2 + colB; a7 = __ldg(p0 + o); b7 = __ldg(p1 + o); }
    if (prC && pcC) { int o = row2 + colC; a8 = __ldg(p0 + o); b8 = __ldg(p1 + o); }

    const int cnt = (1 + (int)prA + (int)prC) * (1 + (int)pcA + (int)pcC);
    const float inv = 1.0f / (float)cnt;

    const float s0 = ((a0 + a1) + (a2 + a3)) + ((a4 + a5) + (a6 + a7)) + a8;
    const float s1 = ((b0 + b1) + (b2 + b3)) + ((b4 + b5) + (b6 + b7)) + b8;

    const int w = 3 * t + rx;       // output column (stride-3 within warp)
    const size_t obase = (size_t)bc * SPATIAL + (size_t)h * WOUT + w;
    out[obase] = s0 * inv;
    out[obase + (size_t)128 * SPATIAL] = s1 * inv;
}

extern "C" void kernel_launch(void* const* d_in, const int* in_sizes, int n_in,
                              void* d_out, int out_size)
{
    const float* in = (const float*)d_in[0];
    float* out = (float*)d_out;
    dim3 grid(HOUT, 128);   // (253 rows, 128 bc-pairs)
    patch2im_kernel<<<grid, 288>>>(in, out);
}